// round 1
// baseline (speedup 1.0000x reference)
#include <cuda_runtime.h>

// Problem constants
#define LATENT  10
#define MAXLEN  80
#define BATCH   512
#define NSTEPS  100
#define HID     64
#define DTC     0.01f

typedef unsigned long long u64;

// ---------------- packed f32x2 helpers (sm_100+) ----------------
__device__ __forceinline__ u64 pk(float x, float y) {
    u64 r;
#if defined(__CUDA_ARCH__) && __CUDA_ARCH__ >= 1000
    asm("mov.b64 %0, {%1, %2};" : "=l"(r) : "f"(x), "f"(y));
#else
    ((float*)&r)[0] = x; ((float*)&r)[1] = y;
#endif
    return r;
}
__device__ __forceinline__ void upk(u64 a, float& x, float& y) {
#if defined(__CUDA_ARCH__) && __CUDA_ARCH__ >= 1000
    asm("mov.b64 {%0, %1}, %2;" : "=f"(x), "=f"(y) : "l"(a));
#else
    x = ((float*)&a)[0]; y = ((float*)&a)[1];
#endif
}
__device__ __forceinline__ u64 fma2_(u64 a, u64 b, u64 c) {
    u64 d;
#if defined(__CUDA_ARCH__) && __CUDA_ARCH__ >= 1000
    asm("fma.rn.f32x2 %0, %1, %2, %3;" : "=l"(d) : "l"(a), "l"(b), "l"(c));
#else
    float ax,ay,bx,by,cx,cy; upk(a,ax,ay); upk(b,bx,by); upk(c,cx,cy);
    d = pk(fmaf(ax,bx,cx), fmaf(ay,by,cy));
#endif
    return d;
}
__device__ __forceinline__ u64 mul2_(u64 a, u64 b) {
    u64 d;
#if defined(__CUDA_ARCH__) && __CUDA_ARCH__ >= 1000
    asm("mul.rn.f32x2 %0, %1, %2;" : "=l"(d) : "l"(a), "l"(b));
#else
    float ax,ay,bx,by; upk(a,ax,ay); upk(b,bx,by); d = pk(ax*bx, ay*by);
#endif
    return d;
}
__device__ __forceinline__ u64 sub2_(u64 a, u64 b) {
    u64 d;
#if defined(__CUDA_ARCH__) && __CUDA_ARCH__ >= 1000
    asm("sub.rn.f32x2 %0, %1, %2;" : "=l"(d) : "l"(a), "l"(b));
#else
    float ax,ay,bx,by; upk(a,ax,ay); upk(b,bx,by); d = pk(ax-bx, ay-by);
#endif
    return d;
}

// One thread = one chain (l, b). Latent dim packed as 5 f32x2 pairs.
// MLP: h_j = relu( sum_{k<12} f_k * W1col[j][k] ),  features f = (xt0..xt9, t, 1)
//      where W1col[j][10] = W1[10][j] (t-weight), W1col[j][11] = b1[j].
// score_e = b2_e + sum_j h_j * W2[j][e]   (W2 rows padded 10 -> 12)
__global__ void __launch_bounds__(128)
vae_sde_kernel(const float* __restrict__ zm,
               const float* __restrict__ zlv,
               const float* __restrict__ W1,
               const float* __restrict__ b1,
               const float* __restrict__ W2,
               const float* __restrict__ b2,
               const float* __restrict__ noise,
               float* __restrict__ out)
{
    // SMEM weights: column-major W1 (12 floats per hidden unit), padded W2 rows
    __shared__ __align__(16) float sW1f[HID * 12];   // 3072 B
    __shared__ __align__(16) float sW2f[HID * 12];   // 3072 B

    const int tid = threadIdx.x;
    for (int i = tid; i < HID * 12; i += 128) {
        int j = i / 12, k = i % 12;
        sW1f[i] = (k < 11) ? W1[k * HID + j] : b1[j];
        sW2f[i] = (k < 10) ? W2[j * 10 + k] : 0.0f;
    }
    __syncthreads();

    const ulonglong2* sW1v = (const ulonglong2*)sW1f;  // [HID*3]
    const ulonglong2* sW2v = (const ulonglong2*)sW2f;
    const u64*        sW2u = (const u64*)sW2f;         // for the (k8,k9) pair

    const int T = blockIdx.x * 128 + tid;      // chain id, < 40960
    const int l = T >> 9;                      // position 0..79
    const int b = T & 511;                     // batch   0..511

    // b2 packed (5 pairs cover latent 10)
    u64 b2r[5];
#pragma unroll
    for (int p = 0; p < 5; p++) b2r[p] = pk(b2[2*p], b2[2*p+1]);

    // ---- per-chain precompute ----
    const float* zmr = zm  + ((size_t)b * MAXLEN + l) * LATENT;
    const float* zvr = zlv + ((size_t)b * MAXLEN + l) * LATENT;

    u64 xt[5], mu2[5], sinv2[5], hv2[5], ssd2[5], err2[5];
#pragma unroll
    for (int p = 0; p < 5; p++) {
        float muv[2], siv[2], hvv[2], ssv[2];
#pragma unroll
        for (int q = 0; q < 2; q++) {
            int d = 2 * p + q;
            float zmc = zmr[d];
            float zmp = (l > 0) ? zmr[d - LATENT] : 0.0f;
            float mu  = zmc - zmp;
            float a_  = (l > 0) ? zvr[d - LATENT] : 0.0f;
            float bb  = zvr[d];
            float mx  = fmaxf(a_, bb);
            float sg  = mx + log1pf(expf(-fabsf(a_ - bb)));   // logaddexp
            float sstd = expf(0.5f * sg);
            float svar = sstd * sstd;
            muv[q] = mu;
            siv[q] = 1.0f / sg;            // logdx = (mu - xt) / sigma
            hvv[q] = 0.5f * svar * DTC;    // drift score coefficient
            ssv[q] = sstd * 0.1f;          // sigma_std * sqrt(dt)
        }
        mu2[p]   = pk(muv[0], muv[1]);
        sinv2[p] = pk(siv[0], siv[1]);
        hv2[p]   = pk(hvv[0], hvv[1]);
        ssd2[p]  = pk(ssv[0], ssv[1]);
        xt[p]    = mu2[p];                 // xt init = mu
        err2[p]  = pk(0.0f, 0.0f);
    }

    const u64 dt2 = pk(DTC, DTC);

    // noise pointer: noise[l, s, b, d], 8B-aligned d-pairs
    const u64* nzp = (const u64*)(noise + ((size_t)l * NSTEPS * BATCH + b) * LATENT);
    const int  nz_stride = BATCH * LATENT / 2;   // u64 units per step

    for (int s = 0; s < NSTEPS; s++) {
        u64 sc[5];
#pragma unroll
        for (int p = 0; p < 5; p++) sc[p] = b2r[p];

        const float t = (float)(l + s) * DTC;
        const u64 f5 = pk(t, 1.0f);

#pragma unroll 8
        for (int j = 0; j < HID; j++) {
            ulonglong2 a0 = sW1v[j * 3 + 0];
            ulonglong2 a1 = sW1v[j * 3 + 1];
            ulonglong2 a2 = sW1v[j * 3 + 2];
            u64 acc = mul2_(xt[0], a0.x);
            acc = fma2_(xt[1], a0.y, acc);
            acc = fma2_(xt[2], a1.x, acc);
            acc = fma2_(xt[3], a1.y, acc);
            acc = fma2_(xt[4], a2.x, acc);
            acc = fma2_(f5,    a2.y, acc);   // + t*w_t + b1
            float hl, hh; upk(acc, hl, hh);
            float h = fmaxf(hl + hh, 0.0f);
            u64 hd = pk(h, h);
            ulonglong2 c0 = sW2v[j * 3 + 0];
            ulonglong2 c1 = sW2v[j * 3 + 1];
            u64        c2 = sW2u[j * 6 + 4];
            sc[0] = fma2_(hd, c0.x, sc[0]);
            sc[1] = fma2_(hd, c0.y, sc[1]);
            sc[2] = fma2_(hd, c1.x, sc[2]);
            sc[3] = fma2_(hd, c1.y, sc[3]);
            sc[4] = fma2_(hd, c2,   sc[4]);
        }

        // elementwise SDE update + score error
#pragma unroll
        for (int p = 0; p < 5; p++) {
            u64 nz    = nzp[p];
            u64 logdx = mul2_(sub2_(mu2[p], xt[p]), sinv2[p]);
            u64 diff  = sub2_(logdx, sc[p]);
            err2[p]   = fma2_(diff, diff, err2[p]);
            u64 x     = fma2_(mu2[p], dt2, xt[p]);     // + mu*dt
            x         = fma2_(sc[p], hv2[p], x);       // + 0.5*var*score*dt
            xt[p]     = fma2_(nz, ssd2[p], x);         // + sstd*sqrt(dt)*dW
        }
        nzp += nz_stride;
    }

    // ---- write outputs: out[0]=sequence, out[1]=mean score error ----
    float2* o0 = (float2*)(out + ((size_t)b * MAXLEN + l) * LATENT);
    float2* o1 = (float2*)(out + (size_t)BATCH * MAXLEN * LATENT
                               + ((size_t)b * MAXLEN + l) * LATENT);
    const float inv_n = 1.0f / (float)NSTEPS;
#pragma unroll
    for (int p = 0; p < 5; p++) {
        float x, y;
        upk(xt[p], x, y);
        o0[p] = make_float2(x, y);
        upk(err2[p], x, y);
        o1[p] = make_float2(x * inv_n, y * inv_n);
    }
}

extern "C" void kernel_launch(void* const* d_in, const int* in_sizes, int n_in,
                              void* d_out, int out_size)
{
    const float* zm    = (const float*)d_in[0];  // z_mean    [512,80,10]
    const float* zlv   = (const float*)d_in[1];  // z_log_var [512,80,10]
    const float* W1    = (const float*)d_in[2];  // [11,64]
    const float* b1    = (const float*)d_in[3];  // [64]
    const float* W2    = (const float*)d_in[4];  // [64,10]
    const float* b2    = (const float*)d_in[5];  // [10]
    const float* noise = (const float*)d_in[6];  // [80,100,512,10]
    float* out = (float*)d_out;                  // [2,512,80,10]

    const int total = BATCH * MAXLEN;            // 40960 chains
    vae_sde_kernel<<<total / 128, 128>>>(zm, zlv, W1, b1, W2, b2, noise, out);
}